// round 2
// baseline (speedup 1.0000x reference)
#include <cuda_runtime.h>
#include <cuda_bf16.h>

#define JNT 24
#define EPSF 1e-6f
#define SH_C0 0.28209479177387814f
#define SH_C1 0.4886025119029199f
#define C20 ( 1.0925484305920792f)
#define C21 (-1.0925484305920792f)
#define C22 ( 0.31539156525252005f)
#define C23 (-1.0925484305920792f)
#define C24 ( 0.5462742152960396f)

typedef unsigned long long u64;

__device__ __forceinline__ u64 pk2(float lo, float hi) {
    u64 r; asm("mov.b64 %0, {%1, %2};" : "=l"(r) : "f"(lo), "f"(hi)); return r;
}
__device__ __forceinline__ void upk2(float& lo, float& hi, u64 v) {
    asm("mov.b64 {%0, %1}, %2;" : "=f"(lo), "=f"(hi) : "l"(v));
}
__device__ __forceinline__ u64 ffma2(u64 a, u64 b, u64 c) {
    u64 d; asm("fma.rn.f32x2 %0, %1, %2, %3;" : "=l"(d) : "l"(a), "l"(b), "l"(c)); return d;
}
__device__ __forceinline__ u64 fmul2(u64 a, u64 b) {
    u64 d; asm("mul.rn.f32x2 %0, %1, %2;" : "=l"(d) : "l"(a), "l"(b)); return d;
}
__device__ __forceinline__ u64 fadd2(u64 a, u64 b) {
    u64 d; asm("add.rn.f32x2 %0, %1, %2;" : "=l"(d) : "l"(a), "l"(b)); return d;
}

// Shared layout per joint (24 duplicated {c,c} pairs, 12 ulonglong2 vectors):
//  [0..11]  : -T rows 0..2 (negated: t00..t23)
//  [12..14] : L0, L1, L2
//  [15]     : base = SH_C0*f0 + 0.5 - C22*f6
//  [16..23] : f1'..f8' pre-scaled SH features
__global__ __launch_bounds__(128)
void shcaster_kernel(const float* __restrict__ xyz,
                     const float* __restrict__ vdir,
                     const float* __restrict__ T,   // [J,4,4]
                     const float* __restrict__ F,   // [J,9]
                     const float* __restrict__ L,   // [J,3]
                     float* __restrict__ out,       // [2*N*3]
                     int N)
{
    __shared__ __align__(16) float2 sJ[JNT][24];

    const int tid = threadIdx.x;
    for (int t = tid; t < JNT * 24; t += blockDim.x) {
        const int j = t / 24, k = t % 24;
        float c;
        if (k < 12) {
            c = -T[j * 16 + k];
        } else if (k < 15) {
            c = L[j * 3 + (k - 12)];
        } else if (k == 15) {
            c = fmaf(SH_C0, F[j * 9 + 0], 0.5f) - C22 * F[j * 9 + 6];
        } else {
            const int m = k - 15;  // 1..8
            float sc;
            switch (m) {
                case 1: sc = -SH_C1;     break;
                case 2: sc =  SH_C1;     break;
                case 3: sc = -SH_C1;     break;
                case 4: sc =  C20;       break;
                case 5: sc =  C21;       break;
                case 6: sc =  3.f * C22; break;
                case 7: sc =  C23;       break;
                default: sc = C24;       break;
            }
            c = sc * F[j * 9 + m];
        }
        sJ[j][k] = make_float2(c, c);
    }
    __syncthreads();

    const int gi = blockIdx.x * blockDim.x + tid;   // pair index
    const int i0 = 2 * gi;
    if (i0 >= N) return;
    const bool hasB = (i0 + 1 < N);

    // Load 2 points + 2 viewdirs, pack per-coordinate across points
    const float2* xp = (const float2*)(xyz + 6 * (size_t)gi);
    const float2* vp = (const float2*)(vdir + 6 * (size_t)gi);
    float2 xa = xp[0];                        // xA0, xA1
    float2 xb = hasB ? xp[1] : make_float2(xyz[3*i0+2], 0.f);  // xA2, xB0
    float2 xc = hasB ? xp[2] : make_float2(0.f, 0.f);          // xB1, xB2
    float2 va = vp[0];
    float2 vb = hasB ? vp[1] : make_float2(vdir[3*i0+2], 0.f);
    float2 vc = hasB ? vp[2] : make_float2(0.f, 0.f);

    const u64 X0 = pk2(xa.x, xb.y);
    const u64 X1 = pk2(xa.y, xc.x);
    const u64 X2 = pk2(xb.x, xc.y);
    const u64 V0 = pk2(va.x, vb.y);
    const u64 V1 = pk2(va.y, vc.x);
    const u64 V2 = pk2(vb.x, vc.y);

    u64 ws = 0ull;                 // {0,0}
    u64 s0 = 0ull, s1 = 0ull, s2 = 0ull;   // sum w * (-(Rx+t))
    u64 e0 = 0ull, e1 = 0ull, e2 = 0ull;   // sum w * (-(Rv))

    const u64 M1 = pk2(-1.f, -1.f);

#pragma unroll
    for (int j = 0; j < JNT; j++) {
        const ulonglong2* jp = reinterpret_cast<const ulonglong2*>(&sJ[j][0]);
        const ulonglong2 p0  = jp[0];   // -t00, -t01
        const ulonglong2 p1  = jp[1];   // -t02, -t03
        const ulonglong2 p2  = jp[2];   // -t10, -t11
        const ulonglong2 p3  = jp[3];   // -t12, -t13
        const ulonglong2 p4  = jp[4];   // -t20, -t21
        const ulonglong2 p5  = jp[5];   // -t22, -t23
        const ulonglong2 p6  = jp[6];   // L0, L1
        const ulonglong2 p7  = jp[7];   // L2, base
        const ulonglong2 p8  = jp[8];   // f1', f2'
        const ulonglong2 p9  = jp[9];   // f3', f4'
        const ulonglong2 p10 = jp[10];  // f5', f6'
        const ulonglong2 p11 = jp[11];  // f7', f8'

        // a = -(R x + tr)  (negated transform)
        const u64 a0 = ffma2(p0.x, X0, ffma2(p0.y, X1, ffma2(p1.x, X2, p1.y)));
        const u64 a1 = ffma2(p2.x, X0, ffma2(p2.y, X1, ffma2(p3.x, X2, p3.y)));
        const u64 a2 = ffma2(p4.x, X0, ffma2(p4.y, X1, ffma2(p5.x, X2, p5.y)));

        // d = L - (Rx+tr) = L + a
        const u64 d0 = fadd2(p6.x, a0);
        const u64 d1 = fadd2(p6.y, a1);
        const u64 d2 = fadd2(p7.x, a2);

        const u64 l2 = ffma2(d0, d0, ffma2(d1, d1, fmul2(d2, d2)));

        float l2A, l2B;
        upk2(l2A, l2B, l2);
        const u64 inv = pk2(rsqrtf(l2A), rsqrtf(l2B));
        const u64 len = fmul2(l2, inv);
        const u64 ux = fmul2(d0, inv);
        const u64 uy = fmul2(d1, inv);
        const u64 uz = fmul2(d2, inv);

        // SH basis dot (pre-scaled features)
        const u64 xy = fmul2(ux, uy);
        const u64 yz = fmul2(uy, uz);
        const u64 xz = fmul2(ux, uz);
        const u64 zz = fmul2(uz, uz);
        const u64 xx = fmul2(ux, ux);
        const u64 nuy = fmul2(uy, M1);
        const u64 pm = ffma2(uy, nuy, xx);  // x^2 - y^2

        u64 rad = p7.y;
        rad = ffma2(uy, p8.x, rad);
        rad = ffma2(uz, p8.y, rad);
        rad = ffma2(ux, p9.x, rad);
        rad = ffma2(xy, p9.y, rad);
        rad = ffma2(yz, p10.x, rad);
        rad = ffma2(zz, p10.y, rad);
        rad = ffma2(xz, p11.x, rad);
        rad = ffma2(pm, p11.y, rad);

        // weights (scalar per lane: relu, rcp)
        float rA, rB, lenA, lenB;
        upk2(rA, rB, rad);
        upk2(lenA, lenB, len);
        rA = fmaxf(rA, 0.f);
        rB = fmaxf(rB, 0.f);
        const float wA = (rA < EPSF) ? 0.f
                        : fmaxf(1.f - __fdividef(lenA, rA), 0.f);
        const float wB = (rB < EPSF) ? 0.f
                        : fmaxf(1.f - __fdividef(lenB, rB), 0.f);
        const u64 w = pk2(wA, wB);

        // b = -(R v)  (rotation only, negated)
        const u64 b0 = ffma2(p0.x, V0, ffma2(p0.y, V1, fmul2(p1.x, V2)));
        const u64 b1 = ffma2(p2.x, V0, ffma2(p2.y, V1, fmul2(p3.x, V2)));
        const u64 b2 = ffma2(p4.x, V0, ffma2(p4.y, V1, fmul2(p5.x, V2)));

        ws = fadd2(ws, w);
        s0 = ffma2(w, a0, s0);
        s1 = ffma2(w, a1, s1);
        s2 = ffma2(w, a2, s2);
        e0 = ffma2(w, b0, e0);
        e1 = ffma2(w, b1, e1);
        e2 = ffma2(w, b2, e2);
    }

    float wsA, wsB, s0A, s0B, s1A, s1B, s2A, s2B, e0A, e0B, e1A, e1B, e2A, e2B;
    upk2(wsA, wsB, ws);
    upk2(s0A, s0B, s0); upk2(s1A, s1B, s1); upk2(s2A, s2B, s2);
    upk2(e0A, e0B, e0); upk2(e1A, e1B, e1); upk2(e2A, e2B, e2);

    const float icA = __fdividef(-1.f, fmaxf(wsA, EPSF));  // negative: undo stored negation
    const float icB = __fdividef(-1.f, fmaxf(wsB, EPSF));
    const bool vA = wsA > EPSF;
    const bool vB = wsB > EPSF;

    const float oA0 = vA ? s0A * icA : xa.x;
    const float oA1 = vA ? s1A * icA : xa.y;
    const float oA2 = vA ? s2A * icA : xb.x;
    const float gA0 = vA ? e0A * icA : va.x;
    const float gA1 = vA ? e1A * icA : va.y;
    const float gA2 = vA ? e2A * icA : vb.x;

    float* o1p = out + 6 * (size_t)gi;
    float* o2p = out + 3 * (size_t)N + 6 * (size_t)gi;

    if (hasB) {
        const float oB0 = vB ? s0B * icB : xb.y;
        const float oB1 = vB ? s1B * icB : xc.x;
        const float oB2 = vB ? s2B * icB : xc.y;
        const float gB0 = vB ? e0B * icB : vb.y;
        const float gB1 = vB ? e1B * icB : vc.x;
        const float gB2 = vB ? e2B * icB : vc.y;
        float2* o1v = (float2*)o1p;
        float2* o2v = (float2*)o2p;
        o1v[0] = make_float2(oA0, oA1);
        o1v[1] = make_float2(oA2, oB0);
        o1v[2] = make_float2(oB1, oB2);
        o2v[0] = make_float2(gA0, gA1);
        o2v[1] = make_float2(gA2, gB0);
        o2v[2] = make_float2(gB1, gB2);
    } else {
        o1p[0] = oA0; o1p[1] = oA1; o1p[2] = oA2;
        o2p[0] = gA0; o2p[1] = gA1; o2p[2] = gA2;
    }
}

extern "C" void kernel_launch(void* const* d_in, const int* in_sizes, int n_in,
                              void* d_out, int out_size)
{
    const float* xyz  = (const float*)d_in[0];
    const float* vdir = (const float*)d_in[1];
    const float* T    = (const float*)d_in[2];
    const float* F    = (const float*)d_in[3];
    const float* L    = (const float*)d_in[4];
    float* out        = (float*)d_out;

    const int N = in_sizes[0] / 3;
    const int nPairs = (N + 1) / 2;
    const int threads = 128;
    const int blocks = (nPairs + threads - 1) / threads;
    shcaster_kernel<<<blocks, threads>>>(xyz, vdir, T, F, L, out, N);
}